// round 1
// baseline (speedup 1.0000x reference)
#include <cuda_runtime.h>
#include <math.h>

// SpatialPositionalEncoding2D: out[b,l,d] = x[b,l,d] + pe(l,d)
// h = w = 128, L = 16384, D = 256, dh = 128, b = 8 (derived at launch).
// pe(l, d):
//   row = l / 128, col = l % 128
//   d <  128: j = d/2,        arg = row * freq[j]
//   d >= 128: j = (d-128)/2,  arg = col * freq[j]
//   freq[j] = exp(-2*j * ln(10000)/128)
//   even d -> sin(arg), odd d -> cos(arg)

namespace {
constexpr int H  = 128;
constexpr int W  = 128;
constexpr int L  = H * W;     // 16384
constexpr int D  = 256;
constexpr int D4 = D / 4;     // 64 float4 per position
constexpr int POS_PER_BLOCK = 4;   // 256 threads = 4 positions x 64 quads
}

__global__ void __launch_bounds__(256, 4)
pe_add_kernel(const float4* __restrict__ x, float4* __restrict__ out, int b)
{
    const int tid = threadIdx.x;
    const int lq  = tid & (D4 - 1);                 // channel-quad index 0..63
    const int l   = (blockIdx.x << 2) + (tid >> 6); // position 0..16383
    const int d0  = lq << 2;                        // first channel of this quad

    const int row = l >> 7;        // l / 128
    const int col = l & (W - 1);   // l % 128

    // All 4 channels in this quad live in the same half (d0 % 4 == 0, split at 128).
    const bool rhalf = (d0 < 128);
    const float pos  = rhalf ? (float)row : (float)col;
    const int   j0   = rhalf ? (d0 >> 1) : ((d0 - 128) >> 1);

    // freq[j] = exp(j * (-2*ln(10000)/128))
    const float KF = -0.14391156831212787f;  // -2*ln(10000)/128
    const float f0 = expf((float)j0 * KF);
    const float f1 = expf((float)(j0 + 1) * KF);

    float s0, c0, s1, c1;
    sincosf(pos * f0, &s0, &c0);
    sincosf(pos * f1, &s1, &c1);
    const float4 pe = make_float4(s0, c0, s1, c1);

    const size_t stride = (size_t)L * D4;          // float4 elements per batch
    const size_t base   = (size_t)l * D4 + lq;

    if (b == 8) {
        // Fast path: fully unrolled, loads batched ahead of stores for MLP.
        float4 v[8];
        #pragma unroll
        for (int bi = 0; bi < 8; bi++) v[bi] = x[base + (size_t)bi * stride];
        #pragma unroll
        for (int bi = 0; bi < 8; bi++) {
            v[bi].x += pe.x; v[bi].y += pe.y; v[bi].z += pe.z; v[bi].w += pe.w;
            out[base + (size_t)bi * stride] = v[bi];
        }
    } else {
        for (int bi = 0; bi < b; bi++) {
            float4 v = x[base + (size_t)bi * stride];
            v.x += pe.x; v.y += pe.y; v.z += pe.z; v.w += pe.w;
            out[base + (size_t)bi * stride] = v;
        }
    }
}

extern "C" void kernel_launch(void* const* d_in, const int* in_sizes, int n_in,
                              void* d_out, int out_size)
{
    const float4* x  = (const float4*)d_in[0];
    float4* out      = (float4*)d_out;
    const int n      = in_sizes[0];          // total elements of x
    const int b      = n / (L * D);          // batch size (8 for this problem)

    const dim3 grid(L / POS_PER_BLOCK);      // 4096 blocks
    const dim3 block(256);
    pe_add_kernel<<<grid, block>>>(x, out, b);
}